// round 1
// baseline (speedup 1.0000x reference)
#include <cuda_runtime.h>
#include <math.h>

// Problem constants
#define BB 2
#define SS 2048
#define EE 1024
#define HH 16
#define DD 64
#define MROWS (BB * SS)   // 4096

// Scratch (allocation-free rule: __device__ globals)
__device__ float g_Q[MROWS * EE];
__device__ float g_K[MROWS * EE];
__device__ float g_V[MROWS * EE];
__device__ float g_O[MROWS * EE];

// ---------------------------------------------------------------------------
// C[M,N] = A[M,K] @ B[N,K]^T   (torch Linear), M=4096, N=K=1024
// 64x64 block tile, 256 threads, 4x4 per thread, K-tile 16.
// ---------------------------------------------------------------------------
__global__ void gemm_nt_kernel(const float* __restrict__ A,
                               const float* __restrict__ Bm,
                               float* __restrict__ C) {
    const int K = EE;
    const int N = EE;
    __shared__ float As[16][64];
    __shared__ float Bs[16][64];

    const int tid = threadIdx.x;            // 0..255
    const int tx = tid & 15;                // col group
    const int ty = tid >> 4;                // row group
    const int row0 = blockIdx.y * 64;
    const int col0 = blockIdx.x * 64;

    float acc[4][4] = {};

    for (int k0 = 0; k0 < K; k0 += 16) {
        // Load 64x16 tiles of A and B (transposed into smem: [k][row])
#pragma unroll
        for (int i = 0; i < 4; i++) {
            int idx = tid + i * 256;        // 0..1023
            int r = idx >> 4;               // 0..63
            int c = idx & 15;               // 0..15
            As[c][r] = A[(size_t)(row0 + r) * K + k0 + c];
            Bs[c][r] = Bm[(size_t)(col0 + r) * K + k0 + c];
        }
        __syncthreads();

#pragma unroll
        for (int kk = 0; kk < 16; kk++) {
            float a[4], b[4];
#pragma unroll
            for (int i = 0; i < 4; i++) {
                a[i] = As[kk][ty * 4 + i];
                b[i] = Bs[kk][tx * 4 + i];
            }
#pragma unroll
            for (int i = 0; i < 4; i++)
#pragma unroll
                for (int j = 0; j < 4; j++)
                    acc[i][j] += a[i] * b[j];
        }
        __syncthreads();
    }

#pragma unroll
    for (int i = 0; i < 4; i++)
#pragma unroll
        for (int j = 0; j < 4; j++)
            C[(size_t)(row0 + ty * 4 + i) * N + col0 + tx * 4 + j] = acc[i][j];
}

// ---------------------------------------------------------------------------
// Interleaved-pair RoPE applied in place on [MROWS, EE] buffer viewed as
// [b, s, h, d]. One thread per (row, head, pair).
// ---------------------------------------------------------------------------
__global__ void rope_kernel(float* __restrict__ X) {
    int idx = blockIdx.x * blockDim.x + threadIdx.x;   // over MROWS * 512
    if (idx >= MROWS * (EE / 2)) return;
    int row = idx >> 9;          // /512
    int p = idx & 511;           // pair slot: h*32 + i
    int s = row & (SS - 1);      // row % SS
    int h = p >> 5;
    int i = p & 31;

    float theta = expf(-logf(10000.0f) * (2.0f * (float)i) / 64.0f);
    float ang = (float)s * theta;
    float c, sn;
    sincosf(ang, &sn, &c);

    size_t base = (size_t)row * EE + h * DD + 2 * i;
    float x1 = X[base];
    float x2 = X[base + 1];
    X[base]     = x1 * c - x2 * sn;
    X[base + 1] = x1 * sn + x2 * c;
}

// ---------------------------------------------------------------------------
// Causal flash attention. Grid: (S/64, B*H). 64 threads/block, one query row
// per thread, online softmax, K/V tiles (64x64) staged in smem.
// Layout of Q/K/V/O: [b*S + s, h*64 + d] row-major (matches GEMM output).
// ---------------------------------------------------------------------------
__global__ void flash_kernel(const float* __restrict__ Q,
                             const float* __restrict__ Kb,
                             const float* __restrict__ V,
                             float* __restrict__ O) {
    const int bh = blockIdx.y;
    const int b = bh / HH;
    const int h = bh % HH;
    const int t = threadIdx.x;              // 0..63
    const int s = blockIdx.x * 64 + t;      // query position

    __shared__ float Ksh[64][64];
    __shared__ float Vsh[64][64];

    float q[64];
    {
        const float* qp = Q + ((size_t)(b * SS + s)) * EE + h * DD;
#pragma unroll
        for (int d = 0; d < 64; d++) q[d] = qp[d];
    }

    float m = -1e30f, l = 0.0f;
    float acc[64] = {};
    const float scale = 1.0f / 32.0f;       // 1/sqrt(E)

    const int ntiles = blockIdx.x + 1;      // causal: only tiles <= query tile
    for (int kt = 0; kt < ntiles; kt++) {
        // Cooperative coalesced tile load: thread t handles column t.
#pragma unroll 4
        for (int i = 0; i < 64; i++) {
            size_t off = ((size_t)(b * SS + kt * 64 + i)) * EE + h * DD + t;
            Ksh[i][t] = Kb[off];
            Vsh[i][t] = V[off];
        }
        __syncthreads();

        const int jmax = (kt == blockIdx.x) ? (s - kt * 64 + 1) : 64;

        float sc[64];
        float tmax = -1e30f;
        for (int j = 0; j < jmax; j++) {
            float acc_s = 0.0f;
#pragma unroll
            for (int d = 0; d < 64; d++) acc_s += q[d] * Ksh[j][d];
            acc_s *= scale;
            sc[j] = acc_s;
            tmax = fmaxf(tmax, acc_s);
        }

        float mnew = fmaxf(m, tmax);
        float corr = __expf(m - mnew);
        l *= corr;
#pragma unroll
        for (int d = 0; d < 64; d++) acc[d] *= corr;

        for (int j = 0; j < jmax; j++) {
            float p = __expf(sc[j] - mnew);
            l += p;
#pragma unroll
            for (int d = 0; d < 64; d++) acc[d] += p * Vsh[j][d];
        }
        m = mnew;
        __syncthreads();
    }

    float inv = 1.0f / l;
    float* op = O + ((size_t)(b * SS + s)) * EE + h * DD;
#pragma unroll
    for (int d = 0; d < 64; d++) op[d] = acc[d] * inv;
}

// ---------------------------------------------------------------------------
// Launch
// ---------------------------------------------------------------------------
extern "C" void kernel_launch(void* const* d_in, const int* in_sizes, int n_in,
                              void* d_out, int out_size) {
    const float* x  = (const float*)d_in[0];
    const float* Wq = (const float*)d_in[1];
    const float* Wk = (const float*)d_in[2];
    const float* Wv = (const float*)d_in[3];
    const float* Wo = (const float*)d_in[4];
    float* out = (float*)d_out;

    float *Qp, *Kp, *Vp, *Op;
    cudaGetSymbolAddress((void**)&Qp, g_Q);
    cudaGetSymbolAddress((void**)&Kp, g_K);
    cudaGetSymbolAddress((void**)&Vp, g_V);
    cudaGetSymbolAddress((void**)&Op, g_O);

    dim3 gemmGrid(EE / 64, MROWS / 64);   // (16, 64)
    dim3 gemmBlock(256);

    gemm_nt_kernel<<<gemmGrid, gemmBlock>>>(x, Wq, Qp);
    gemm_nt_kernel<<<gemmGrid, gemmBlock>>>(x, Wk, Kp);
    gemm_nt_kernel<<<gemmGrid, gemmBlock>>>(x, Wv, Vp);

    int ropeN = MROWS * (EE / 2);
    rope_kernel<<<(ropeN + 255) / 256, 256>>>(Qp);
    rope_kernel<<<(ropeN + 255) / 256, 256>>>(Kp);

    dim3 flashGrid(SS / 64, BB * HH);     // (32, 32)
    flash_kernel<<<flashGrid, 64>>>(Qp, Kp, Vp, Op);

    gemm_nt_kernel<<<gemmGrid, gemmBlock>>>(Op, Wo, out);
}

// round 4
// speedup vs baseline: 2.0851x; 2.0851x over previous
#include <cuda_runtime.h>
#include <cuda_bf16.h>
#include <math.h>
#include <stdint.h>

// Problem constants
#define BB 2
#define SS 2048
#define EE 1024
#define HH 16
#define DD 64
#define MROWS (BB * SS)   // 4096

// Scratch (__device__ globals; allocation-free rule)
__device__ float g_Q[MROWS * EE];
__device__ float g_K[MROWS * EE];
__device__ float g_V[MROWS * EE];
__device__ float g_O[MROWS * EE];
__device__ __nv_bfloat16 g_ahi[MROWS * EE];
__device__ __nv_bfloat16 g_alo[MROWS * EE];
__device__ __nv_bfloat16 g_whi[EE * EE];
__device__ __nv_bfloat16 g_wlo[EE * EE];

// ---------------------------------------------------------------------------
// Helpers
// ---------------------------------------------------------------------------
static __device__ __forceinline__ uint32_t smem_u32(const void* p) {
    uint32_t a;
    asm("{ .reg .u64 t; cvta.to.shared.u64 t, %1; cvt.u32.u64 %0, t; }"
        : "=r"(a) : "l"(p));
    return a;
}

#define SWZ(o) ((o) ^ (((o) >> 3) & 0x70))

static __device__ __forceinline__ void cp16(uint32_t saddr, const void* g) {
    asm volatile("cp.async.cg.shared.global [%0], [%1], 16;"
                 :: "r"(saddr), "l"(g));
}
#define CP_COMMIT() asm volatile("cp.async.commit_group;")
#define CP_WAIT(n)  asm volatile("cp.async.wait_group %0;" :: "n"(n))

static __device__ __forceinline__ void ldsm4(uint32_t* r, uint32_t addr) {
    asm volatile("ldmatrix.sync.aligned.m8n8.x4.shared.b16 {%0,%1,%2,%3}, [%4];"
                 : "=r"(r[0]), "=r"(r[1]), "=r"(r[2]), "=r"(r[3]) : "r"(addr));
}

static __device__ __forceinline__ void mma_bf16(float* c, const uint32_t* a,
                                                const uint32_t* b) {
    asm volatile(
        "mma.sync.aligned.m16n8k16.row.col.f32.bf16.bf16.f32 "
        "{%0,%1,%2,%3}, {%4,%5,%6,%7}, {%8,%9}, {%0,%1,%2,%3};"
        : "+f"(c[0]), "+f"(c[1]), "+f"(c[2]), "+f"(c[3])
        : "r"(a[0]), "r"(a[1]), "r"(a[2]), "r"(a[3]), "r"(b[0]), "r"(b[1]));
}

// ---------------------------------------------------------------------------
// fp32 -> bf16 hi/lo split
// ---------------------------------------------------------------------------
__global__ void split_kernel(const float* __restrict__ src,
                             __nv_bfloat16* __restrict__ hi,
                             __nv_bfloat16* __restrict__ lo, int n) {
    int i = blockIdx.x * blockDim.x + threadIdx.x;
    if (i >= n) return;
    float x = src[i];
    __nv_bfloat16 h = __float2bfloat16(x);
    hi[i] = h;
    lo[i] = __float2bfloat16(x - __bfloat162float(h));
}

// ---------------------------------------------------------------------------
// Warp-MMA GEMM: C[M,N] = (Ahi+Alo)[M,K] @ (Bhi+Blo)[N,K]^T, fp32 out.
// M=4096, N=K=1024. CTA 128x128, BK=64, 8 warps (64x32 warp tiles),
// cp.async double buffer, SW128-swizzled smem, ldmatrix fragments,
// 3-term compensated bf16 mma (hi*hi + hi*lo + lo*hi).
// ---------------------------------------------------------------------------
#define BM 128
#define BN 128
#define BK 64
#define KTILES (EE / BK)                 // 16
#define TILE_B (BM * BK * 2)             // 16384 bytes per tile
#define STAGE_B (4 * TILE_B)             // 65536 (Ahi,Alo,Bhi,Blo)
#define GEMM_SMEM (2 * STAGE_B)          // 131072

__global__ void __launch_bounds__(256) gemm_mma(
    const __nv_bfloat16* __restrict__ Ahi, const __nv_bfloat16* __restrict__ Alo,
    const __nv_bfloat16* __restrict__ Bhi, const __nv_bfloat16* __restrict__ Blo,
    float* __restrict__ C) {
    extern __shared__ __align__(1024) char smem[];
    const uint32_t sb = smem_u32(smem);

    const int tid = threadIdx.x;
    const int wid = tid >> 5;
    const int lid = tid & 31;
    const int row0 = blockIdx.y * BM;
    const int col0 = blockIdx.x * BN;
    const int wm = wid & 1;               // 2 m-groups of 64
    const int wn = wid >> 1;              // 4 n-groups of 32

    // Per-stage tile byte offsets
    const int O_AHI = 0, O_ALO = TILE_B, O_BHI = 2 * TILE_B, O_BLO = 3 * TILE_B;

    float acc[4][4][4] = {};              // [mt][nt][frag]

    // ---- async tile loader: stage st, k-tile kt ----
    auto load_tiles = [&](int st, int kt) {
        const uint32_t stb = sb + st * STAGE_B;
        const int k0 = kt * BK;
#pragma unroll
        for (int i = 0; i < 4; i++) {
            int c = tid + i * 256;        // 0..1023 chunk id
            int r = c >> 3;               // 0..127
            int cb = (c & 7) * 16;        // byte col 0..112
            uint32_t so = SWZ((uint32_t)(r * 128 + cb));
            size_t ga = (size_t)(row0 + r) * EE + k0 + (c & 7) * 8;
            size_t gb = (size_t)(col0 + r) * EE + k0 + (c & 7) * 8;
            cp16(stb + O_AHI + so, Ahi + ga);
            cp16(stb + O_ALO + so, Alo + ga);
            cp16(stb + O_BHI + so, Bhi + gb);
            cp16(stb + O_BLO + so, Blo + gb);
        }
    };

    load_tiles(0, 0);
    CP_COMMIT();

    for (int kt = 0; kt < KTILES; kt++) {
        if (kt + 1 < KTILES) {
            load_tiles((kt + 1) & 1, kt + 1);
            CP_COMMIT();
            CP_WAIT(1);
        } else {
            CP_WAIT(0);
        }
        __syncthreads();

        const uint32_t stb = sb + (kt & 1) * STAGE_B;
        // lane-derived ldmatrix addressing
        const int q = lid >> 3, rin = lid & 7;
        const int arow = wm * 64 + (q & 1) * 8 + rin;
        const int brow = wn * 32 + (q >> 1) * 8 + rin;
        const int akb = (q >> 1) * 16;    // A k-byte offset within kstep
        const int bkb = (q & 1) * 16;     // B k-byte offset within kstep

#pragma unroll
        for (int ks = 0; ks < 4; ks++) {
            const int kb = ks * 32;       // 16 bf16 = 32B per kstep
            uint32_t ahi[4][4], alo[4][4], bhi[2][4], blo[2][4];
#pragma unroll
            for (int mt = 0; mt < 4; mt++) {
                uint32_t off = SWZ((uint32_t)((arow + mt * 16) * 128 + kb + akb));
                ldsm4(ahi[mt], stb + O_AHI + off);
                ldsm4(alo[mt], stb + O_ALO + off);
            }
#pragma unroll
            for (int p = 0; p < 2; p++) {
                uint32_t off = SWZ((uint32_t)((brow + p * 16) * 128 + kb + bkb));
                ldsm4(bhi[p], stb + O_BHI + off);
                ldsm4(blo[p], stb + O_BLO + off);
            }
#pragma unroll
            for (int mt = 0; mt < 4; mt++)
#pragma unroll
                for (int nt = 0; nt < 4; nt++) {
                    const uint32_t* bh = &bhi[nt >> 1][(nt & 1) * 2];
                    const uint32_t* bl = &blo[nt >> 1][(nt & 1) * 2];
                    mma_bf16(acc[mt][nt], ahi[mt], bh);
                    mma_bf16(acc[mt][nt], ahi[mt], bl);
                    mma_bf16(acc[mt][nt], alo[mt], bh);
                }
        }
        __syncthreads();
    }

    // Epilogue: fragment layout -> C
    const int r_base = row0 + wm * 64 + (lid >> 2);
    const int c_base = col0 + wn * 32 + (lid & 3) * 2;
#pragma unroll
    for (int mt = 0; mt < 4; mt++)
#pragma unroll
        for (int nt = 0; nt < 4; nt++) {
            int r = r_base + mt * 16;
            int c = c_base + nt * 8;
            *reinterpret_cast<float2*>(C + (size_t)r * EE + c) =
                make_float2(acc[mt][nt][0], acc[mt][nt][1]);
            *reinterpret_cast<float2*>(C + (size_t)(r + 8) * EE + c) =
                make_float2(acc[mt][nt][2], acc[mt][nt][3]);
        }
}

// ---------------------------------------------------------------------------
// Interleaved-pair RoPE in place on [MROWS, EE] viewed as [b,s,h,d].
// ---------------------------------------------------------------------------
__global__ void rope_kernel(float* __restrict__ X) {
    int idx = blockIdx.x * blockDim.x + threadIdx.x;
    if (idx >= MROWS * (EE / 2)) return;
    int row = idx >> 9;
    int p = idx & 511;
    int s = row & (SS - 1);
    int h = p >> 5;
    int i = p & 31;

    float theta = expf(-logf(10000.0f) * (2.0f * (float)i) / 64.0f);
    float ang = (float)s * theta;
    float c, sn;
    sincosf(ang, &sn, &c);

    size_t base = (size_t)row * EE + h * DD + 2 * i;
    float x1 = X[base];
    float x2 = X[base + 1];
    X[base]     = x1 * c - x2 * sn;
    X[base + 1] = x1 * sn + x2 * c;
}

// ---------------------------------------------------------------------------
// Causal flash attention, one query per thread, chunked score buffer.
// ---------------------------------------------------------------------------
__global__ void __launch_bounds__(64) flash_kernel(const float* __restrict__ Q,
                                                   const float* __restrict__ Kb,
                                                   const float* __restrict__ V,
                                                   float* __restrict__ O) {
    const int bh = blockIdx.y;
    const int b = bh / HH;
    const int h = bh % HH;
    const int t = threadIdx.x;
    const int s = blockIdx.x * 64 + t;

    __shared__ float Ksh[64][64];
    __shared__ float Vsh[64][64];

    float q[64];
    {
        const float* qp = Q + ((size_t)(b * SS + s)) * EE + h * DD;
#pragma unroll
        for (int d = 0; d < 64; d++) q[d] = qp[d];
    }

    float m = -1e30f, l = 0.0f;
    float acc[64] = {};
    const float scale = 1.0f / 32.0f;

    const int ntiles = blockIdx.x + 1;
    for (int kt = 0; kt < ntiles; kt++) {
#pragma unroll 4
        for (int i = 0; i < 64; i++) {
            size_t off = ((size_t)(b * SS + kt * 64 + i)) * EE + h * DD + t;
            Ksh[i][t] = Kb[off];
            Vsh[i][t] = V[off];
        }
        __syncthreads();

        const int jmax = (kt == blockIdx.x) ? (s - kt * 64 + 1) : 64;

        for (int j0 = 0; j0 < jmax; j0 += 16) {
            const int jn = (jmax - j0 < 16) ? (jmax - j0) : 16;
            float sc[16];
            float tmax = -1e30f;
            for (int jj = 0; jj < jn; jj++) {
                float acc_s = 0.0f;
#pragma unroll
                for (int d = 0; d < 64; d++) acc_s += q[d] * Ksh[j0 + jj][d];
                acc_s *= scale;
                sc[jj] = acc_s;
                tmax = fmaxf(tmax, acc_s);
            }
            float mnew = fmaxf(m, tmax);
            float corr = __expf(m - mnew);
            l *= corr;
#pragma unroll
            for (int d = 0; d < 64; d++) acc[d] *= corr;
            for (int jj = 0; jj < jn; jj++) {
                float p = __expf(sc[jj] - mnew);
                l += p;
#pragma unroll
                for (int d = 0; d < 64; d++) acc[d] += p * Vsh[j0 + jj][d];
            }
            m = mnew;
        }
        __syncthreads();
    }

    float inv = 1.0f / l;
    float* op = O + ((size_t)(b * SS + s)) * EE + h * DD;
#pragma unroll
    for (int d = 0; d < 64; d++) op[d] = acc[d] * inv;
}

// ---------------------------------------------------------------------------
// Launch
// ---------------------------------------------------------------------------
extern "C" void kernel_launch(void* const* d_in, const int* in_sizes, int n_in,
                              void* d_out, int out_size) {
    const float* x  = (const float*)d_in[0];
    const float* Wq = (const float*)d_in[1];
    const float* Wk = (const float*)d_in[2];
    const float* Wv = (const float*)d_in[3];
    const float* Wo = (const float*)d_in[4];
    float* out = (float*)d_out;

    float *Qp, *Kp, *Vp, *Op;
    __nv_bfloat16 *ahi, *alo, *whi, *wlo;
    cudaGetSymbolAddress((void**)&Qp, g_Q);
    cudaGetSymbolAddress((void**)&Kp, g_K);
    cudaGetSymbolAddress((void**)&Vp, g_V);
    cudaGetSymbolAddress((void**)&Op, g_O);
    cudaGetSymbolAddress((void**)&ahi, g_ahi);
    cudaGetSymbolAddress((void**)&alo, g_alo);
    cudaGetSymbolAddress((void**)&whi, g_whi);
    cudaGetSymbolAddress((void**)&wlo, g_wlo);

    cudaFuncSetAttribute(gemm_mma, cudaFuncAttributeMaxDynamicSharedMemorySize,
                         GEMM_SMEM);

    const int nA = MROWS * EE;
    const int nW = EE * EE;
    dim3 gg(EE / BN, MROWS / BM);   // (8, 32)

    split_kernel<<<(nA + 255) / 256, 256>>>(x, ahi, alo, nA);

    split_kernel<<<(nW + 255) / 256, 256>>>(Wq, whi, wlo, nW);
    gemm_mma<<<gg, 256, GEMM_SMEM>>>(ahi, alo, whi, wlo, Qp);

    split_kernel<<<(nW + 255) / 256, 256>>>(Wk, whi, wlo, nW);
    gemm_mma<<<gg, 256, GEMM_SMEM>>>(ahi, alo, whi, wlo, Kp);

    split_kernel<<<(nW + 255) / 256, 256>>>(Wv, whi, wlo, nW);
    gemm_mma<<<gg, 256, GEMM_SMEM>>>(ahi, alo, whi, wlo, Vp);

    int ropeN = MROWS * (EE / 2);
    rope_kernel<<<(ropeN + 255) / 256, 256>>>(Qp);
    rope_kernel<<<(ropeN + 255) / 256, 256>>>(Kp);

    dim3 flashGrid(SS / 64, BB * HH);   // (32, 32)
    flash_kernel<<<flashGrid, 64>>>(Qp, Kp, Vp, Op);

    split_kernel<<<(nA + 255) / 256, 256>>>(Op, ahi, alo, nA);
    split_kernel<<<(nW + 255) / 256, 256>>>(Wo, whi, wlo, nW);
    gemm_mma<<<gg, 256, GEMM_SMEM>>>(ahi, alo, whi, wlo, out);
}

// round 5
// speedup vs baseline: 5.5858x; 2.6789x over previous
#include <cuda_runtime.h>
#include <cuda_bf16.h>
#include <math.h>
#include <stdint.h>

// Problem constants
#define BB 2
#define SS 2048
#define EE 1024
#define HH 16
#define DD 64
#define MROWS (BB * SS)   // 4096

// Scratch (__device__ globals; allocation-free rule)
__device__ __nv_bfloat16 g_ahi[MROWS * EE];
__device__ __nv_bfloat16 g_alo[MROWS * EE];
__device__ __nv_bfloat16 g_whi[EE * EE];
__device__ __nv_bfloat16 g_wlo[EE * EE];
__device__ __nv_bfloat16 g_qhi[MROWS * EE];
__device__ __nv_bfloat16 g_qlo[MROWS * EE];
__device__ __nv_bfloat16 g_khi[MROWS * EE];
__device__ __nv_bfloat16 g_klo[MROWS * EE];
__device__ __nv_bfloat16 g_vhi[MROWS * EE];
__device__ __nv_bfloat16 g_vlo[MROWS * EE];
__device__ float2 g_rope[SS * 32];

// ---------------------------------------------------------------------------
// Helpers
// ---------------------------------------------------------------------------
static __device__ __forceinline__ uint32_t smem_u32(const void* p) {
    uint32_t a;
    asm("{ .reg .u64 t; cvta.to.shared.u64 t, %1; cvt.u32.u64 %0, t; }"
        : "=r"(a) : "l"(p));
    return a;
}

#define SWZ(o) ((o) ^ (((o) >> 3) & 0x70))

static __device__ __forceinline__ void cp16(uint32_t saddr, const void* g) {
    asm volatile("cp.async.cg.shared.global [%0], [%1], 16;"
                 :: "r"(saddr), "l"(g));
}
#define CP_COMMIT() asm volatile("cp.async.commit_group;")
#define CP_WAIT(n)  asm volatile("cp.async.wait_group %0;" :: "n"(n))

static __device__ __forceinline__ void ldsm4(uint32_t* r, uint32_t addr) {
    asm volatile("ldmatrix.sync.aligned.m8n8.x4.shared.b16 {%0,%1,%2,%3}, [%4];"
                 : "=r"(r[0]), "=r"(r[1]), "=r"(r[2]), "=r"(r[3]) : "r"(addr));
}

static __device__ __forceinline__ void ldsm4t(uint32_t* r, uint32_t addr) {
    asm volatile("ldmatrix.sync.aligned.m8n8.x4.trans.shared.b16 {%0,%1,%2,%3}, [%4];"
                 : "=r"(r[0]), "=r"(r[1]), "=r"(r[2]), "=r"(r[3]) : "r"(addr));
}

static __device__ __forceinline__ void mma_bf16(float* c, const uint32_t* a,
                                                const uint32_t* b) {
    asm volatile(
        "mma.sync.aligned.m16n8k16.row.col.f32.bf16.bf16.f32 "
        "{%0,%1,%2,%3}, {%4,%5,%6,%7}, {%8,%9}, {%0,%1,%2,%3};"
        : "+f"(c[0]), "+f"(c[1]), "+f"(c[2]), "+f"(c[3])
        : "r"(a[0]), "r"(a[1]), "r"(a[2]), "r"(a[3]), "r"(b[0]), "r"(b[1]));
}

// FFMA-only exp (no MUFU): exp(x) = 2^(x*log2e), |rel err| ~2e-6
static __device__ __forceinline__ float fast_exp(float x) {
    float t = x * 1.4426950408889634f;
    t = fmaxf(t, -126.0f);
    float fn = t + 12582912.0f;                    // round-to-nearest magic
    int n = __float_as_int(fn) - 0x4B400000;
    float f = t - (fn - 12582912.0f);              // f in [-0.5, 0.5]
    float r = 0.0013333558f;
    r = fmaf(r, f, 0.0096181291f);
    r = fmaf(r, f, 0.0555041087f);
    r = fmaf(r, f, 0.2402265069f);
    r = fmaf(r, f, 0.6931471806f);
    r = fmaf(r, f, 1.0f);
    return __int_as_float(__float_as_int(r) + (n << 23));
}

static __device__ __forceinline__ uint32_t pack_bf2(__nv_bfloat16 lo, __nv_bfloat16 hi) {
    __nv_bfloat162 v = {lo, hi};   // .x in low half
    return *reinterpret_cast<uint32_t*>(&v);
}

// ---------------------------------------------------------------------------
// rope cos/sin table:  tab[s*32 + i] = (cos, sin) of s / 10000^(2i/64)
// ---------------------------------------------------------------------------
__global__ void rope_table_kernel() {
    int idx = blockIdx.x * blockDim.x + threadIdx.x;
    if (idx >= SS * 32) return;
    int s = idx >> 5, i = idx & 31;
    float theta = expf(-logf(10000.0f) * (2.0f * (float)i) / 64.0f);
    float c, sn;
    sincosf((float)s * theta, &sn, &c);
    g_rope[idx] = make_float2(c, sn);
}

// ---------------------------------------------------------------------------
// fp32 -> bf16 hi/lo split
// ---------------------------------------------------------------------------
__global__ void split_kernel(const float* __restrict__ src,
                             __nv_bfloat16* __restrict__ hi,
                             __nv_bfloat16* __restrict__ lo, int n) {
    int i = blockIdx.x * blockDim.x + threadIdx.x;
    if (i >= n) return;
    float x = src[i];
    __nv_bfloat16 h = __float2bfloat16(x);
    hi[i] = h;
    lo[i] = __float2bfloat16(x - __bfloat162float(h));
}

// ---------------------------------------------------------------------------
// Warp-MMA GEMM: C[M,N] = (Ahi+Alo)[M,K] @ (Bhi+Blo)[N,K]^T.
// mode 0: fp32 C.  mode 1: rope + hi/lo bf16 to BHSD.  mode 2: hi/lo BHSD.
// ---------------------------------------------------------------------------
#define BM 128
#define BN 128
#define BK 64
#define KTILES (EE / BK)                 // 16
#define TILE_B (BM * BK * 2)             // 16384
#define STAGE_B (4 * TILE_B)             // 65536
#define GEMM_SMEM (2 * STAGE_B)          // 131072

__global__ void __launch_bounds__(256) gemm_mma(
    const __nv_bfloat16* __restrict__ Ahi, const __nv_bfloat16* __restrict__ Alo,
    const __nv_bfloat16* __restrict__ Bhi, const __nv_bfloat16* __restrict__ Blo,
    float* __restrict__ C,
    __nv_bfloat16* __restrict__ Dhi, __nv_bfloat16* __restrict__ Dlo,
    int mode) {
    extern __shared__ __align__(1024) char smem[];
    const uint32_t sb = smem_u32(smem);

    const int tid = threadIdx.x;
    const int wid = tid >> 5;
    const int lid = tid & 31;
    const int row0 = blockIdx.y * BM;
    const int col0 = blockIdx.x * BN;
    const int wm = wid & 1;
    const int wn = wid >> 1;

    const int O_AHI = 0, O_ALO = TILE_B, O_BHI = 2 * TILE_B, O_BLO = 3 * TILE_B;

    float acc[4][4][4] = {};

    auto load_tiles = [&](int st, int kt) {
        const uint32_t stb = sb + st * STAGE_B;
        const int k0 = kt * BK;
#pragma unroll
        for (int i = 0; i < 4; i++) {
            int c = tid + i * 256;
            int r = c >> 3;
            int cb = (c & 7) * 16;
            uint32_t so = SWZ((uint32_t)(r * 128 + cb));
            size_t ga = (size_t)(row0 + r) * EE + k0 + (c & 7) * 8;
            size_t gb = (size_t)(col0 + r) * EE + k0 + (c & 7) * 8;
            cp16(stb + O_AHI + so, Ahi + ga);
            cp16(stb + O_ALO + so, Alo + ga);
            cp16(stb + O_BHI + so, Bhi + gb);
            cp16(stb + O_BLO + so, Blo + gb);
        }
    };

    load_tiles(0, 0);
    CP_COMMIT();

    for (int kt = 0; kt < KTILES; kt++) {
        if (kt + 1 < KTILES) {
            load_tiles((kt + 1) & 1, kt + 1);
            CP_COMMIT();
            CP_WAIT(1);
        } else {
            CP_WAIT(0);
        }
        __syncthreads();

        const uint32_t stb = sb + (kt & 1) * STAGE_B;
        const int q = lid >> 3, rin = lid & 7;
        const int arow = wm * 64 + (q & 1) * 8 + rin;
        const int brow = wn * 32 + (q >> 1) * 8 + rin;
        const int akb = (q >> 1) * 16;
        const int bkb = (q & 1) * 16;

#pragma unroll
        for (int ks = 0; ks < 4; ks++) {
            const int kb = ks * 32;
            uint32_t ahi[4][4], alo[4][4], bhi[2][4], blo[2][4];
#pragma unroll
            for (int mt = 0; mt < 4; mt++) {
                uint32_t off = SWZ((uint32_t)((arow + mt * 16) * 128 + kb + akb));
                ldsm4(ahi[mt], stb + O_AHI + off);
                ldsm4(alo[mt], stb + O_ALO + off);
            }
#pragma unroll
            for (int p = 0; p < 2; p++) {
                uint32_t off = SWZ((uint32_t)((brow + p * 16) * 128 + kb + bkb));
                ldsm4(bhi[p], stb + O_BHI + off);
                ldsm4(blo[p], stb + O_BLO + off);
            }
#pragma unroll
            for (int mt = 0; mt < 4; mt++)
#pragma unroll
                for (int nt = 0; nt < 4; nt++) {
                    const uint32_t* bh = &bhi[nt >> 1][(nt & 1) * 2];
                    const uint32_t* bl = &blo[nt >> 1][(nt & 1) * 2];
                    mma_bf16(acc[mt][nt], ahi[mt], bh);
                    mma_bf16(acc[mt][nt], ahi[mt], bl);
                    mma_bf16(acc[mt][nt], alo[mt], bh);
                }
        }
        __syncthreads();
    }

    const int r_base = row0 + wm * 64 + (lid >> 2);
    const int c_base = col0 + wn * 32 + (lid & 3) * 2;

    if (mode == 0) {
#pragma unroll
        for (int mt = 0; mt < 4; mt++)
#pragma unroll
            for (int nt = 0; nt < 4; nt++) {
                int r = r_base + mt * 16;
                int c = c_base + nt * 8;
                *reinterpret_cast<float2*>(C + (size_t)r * EE + c) =
                    make_float2(acc[mt][nt][0], acc[mt][nt][1]);
                *reinterpret_cast<float2*>(C + (size_t)(r + 8) * EE + c) =
                    make_float2(acc[mt][nt][2], acc[mt][nt][3]);
            }
    } else {
#pragma unroll
        for (int mt = 0; mt < 4; mt++)
#pragma unroll
            for (int nt = 0; nt < 4; nt++) {
                int gr = r_base + mt * 16;
                int gc = c_base + nt * 8;
                int hh = gc >> 6, d = gc & 63, ii = d >> 1;
                int b_ = gr >> 11;
                int s1 = gr & (SS - 1);
                int s2 = (gr + 8) & (SS - 1);
                float v0 = acc[mt][nt][0], v1 = acc[mt][nt][1];
                float v2 = acc[mt][nt][2], v3 = acc[mt][nt][3];
                if (mode == 1) {
                    float2 cs1 = g_rope[(s1 << 5) + ii];
                    float2 cs2 = g_rope[(s2 << 5) + ii];
                    float t0 = v0 * cs1.x - v1 * cs1.y;
                    v1 = v0 * cs1.y + v1 * cs1.x; v0 = t0;
                    t0 = v2 * cs2.x - v3 * cs2.y;
                    v3 = v2 * cs2.y + v3 * cs2.x; v2 = t0;
                }
                size_t o1 = ((size_t)((b_ * HH + hh) * SS + s1)) * 64 + d;
                size_t o2 = ((size_t)((b_ * HH + hh) * SS + s2)) * 64 + d;
                __nv_bfloat16 h0 = __float2bfloat16(v0), h1 = __float2bfloat16(v1);
                __nv_bfloat16 h2 = __float2bfloat16(v2), h3 = __float2bfloat16(v3);
                *reinterpret_cast<uint32_t*>(Dhi + o1) = pack_bf2(h0, h1);
                *reinterpret_cast<uint32_t*>(Dhi + o2) = pack_bf2(h2, h3);
                *reinterpret_cast<uint32_t*>(Dlo + o1) = pack_bf2(
                    __float2bfloat16(v0 - __bfloat162float(h0)),
                    __float2bfloat16(v1 - __bfloat162float(h1)));
                *reinterpret_cast<uint32_t*>(Dlo + o2) = pack_bf2(
                    __float2bfloat16(v2 - __bfloat162float(h2)),
                    __float2bfloat16(v3 - __bfloat162float(h3)));
            }
    }
}

// ---------------------------------------------------------------------------
// Warp-MMA causal flash attention. Grid (S/128, B*H), 128 threads (4 warps).
// Per warp: 32 q rows. K-tile 64. 3-term bf16 hi/lo for QK and PV.
// Inputs per-head contiguous [bh, s, 64]. Output: split bf16 into [row, E].
// ---------------------------------------------------------------------------
#define FQ 128
#define FK 64
#define Q_B 16384                     // bytes per Q tile (hi or lo)
#define KV_STAGE 32768                // Khi,Klo,Vhi,Vlo tiles (8KB each)
#define FLASH_SMEM (2 * Q_B + 2 * KV_STAGE)   // 98304

__global__ void __launch_bounds__(128) flash_mma(
    const __nv_bfloat16* __restrict__ qhi, const __nv_bfloat16* __restrict__ qlo,
    const __nv_bfloat16* __restrict__ khi, const __nv_bfloat16* __restrict__ klo,
    const __nv_bfloat16* __restrict__ vhi, const __nv_bfloat16* __restrict__ vlo,
    __nv_bfloat16* __restrict__ ohi, __nv_bfloat16* __restrict__ olo) {
    extern __shared__ __align__(1024) char smem[];
    const uint32_t sb = smem_u32(smem);
    const int tid = threadIdx.x;
    const int wid = tid >> 5;
    const int lid = tid & 31;
    const int bh = blockIdx.y;
    const int qt = gridDim.x - 1 - blockIdx.x;   // heavy tiles first
    const int q0 = qt * FQ;
    const int b = bh >> 4, h = bh & 15;

    // ---- load Q tiles (hi at sb+0, lo at sb+Q_B) ----
#pragma unroll
    for (int i = 0; i < 8; i++) {
        int c = i * 128 + tid;       // 0..1023
        int r = c >> 3, cb = c & 7;
        uint32_t so = SWZ((uint32_t)(r * 128 + cb * 16));
        size_t g = ((size_t)bh * SS + q0 + r) * 64 + cb * 8;
        cp16(sb + so, qhi + g);
        cp16(sb + Q_B + so, qlo + g);
    }
    CP_COMMIT();

    auto load_kv = [&](int st, int kt) {
        const uint32_t stb = sb + 2 * Q_B + st * KV_STAGE;
        const size_t rb = (size_t)bh * SS + (size_t)kt * FK;
#pragma unroll
        for (int i = 0; i < 4; i++) {
            int c = i * 128 + tid;   // 0..511
            int r = c >> 3, cb = c & 7;
            uint32_t so = SWZ((uint32_t)(r * 128 + cb * 16));
            size_t g = (rb + r) * 64 + cb * 8;
            cp16(stb + so,         khi + g);
            cp16(stb + 8192 + so,  klo + g);
            cp16(stb + 16384 + so, vhi + g);
            cp16(stb + 24576 + so, vlo + g);
        }
    };

    float o[2][8][4] = {};
    float mrow[4] = {-1e30f, -1e30f, -1e30f, -1e30f};
    float lrow[4] = {};

    const int nkt = 2 * qt + 2;
    load_kv(0, 0);
    CP_COMMIT();

    const int qq = lid >> 3, rin = lid & 7;
    const float sc = 1.0f / 32.0f;

    for (int kt = 0; kt < nkt; kt++) {
        if (kt + 1 < nkt) {
            load_kv((kt + 1) & 1, kt + 1);
            CP_COMMIT();
            CP_WAIT(1);
        } else {
            CP_WAIT(0);
        }
        __syncthreads();

        const uint32_t stb = sb + 2 * Q_B + (kt & 1) * KV_STAGE;
        const int k0 = kt * FK;

        // ---- S = Q K^T (3-term) ----
        float s[2][8][4] = {};
#pragma unroll
        for (int kd = 0; kd < 4; kd++) {
            uint32_t qh[2][4], ql[2][4];
#pragma unroll
            for (int mt = 0; mt < 2; mt++) {
                uint32_t off = SWZ((uint32_t)(
                    (wid * 32 + mt * 16 + (qq & 1) * 8 + rin) * 128 +
                    kd * 32 + (qq >> 1) * 16));
                ldsm4(qh[mt], sb + off);
                ldsm4(ql[mt], sb + Q_B + off);
            }
            uint32_t kh[4][4], kl[4][4];
#pragma unroll
            for (int p = 0; p < 4; p++) {
                uint32_t off = SWZ((uint32_t)(
                    (p * 16 + (qq >> 1) * 8 + rin) * 128 + kd * 32 + (qq & 1) * 16));
                ldsm4(kh[p], stb + off);
                ldsm4(kl[p], stb + 8192 + off);
            }
#pragma unroll
            for (int mt = 0; mt < 2; mt++)
#pragma unroll
                for (int nt = 0; nt < 8; nt++) {
                    const uint32_t* bhp = &kh[nt >> 1][(nt & 1) * 2];
                    const uint32_t* blp = &kl[nt >> 1][(nt & 1) * 2];
                    mma_bf16(s[mt][nt], qh[mt], bhp);
                    mma_bf16(s[mt][nt], qh[mt], blp);
                    mma_bf16(s[mt][nt], ql[mt], bhp);
                }
        }

        // scale + causal mask (only the 2 diagonal-band tiles need it)
        const bool need_mask = (k0 + FK - 1) > (q0 + wid * 32);
#pragma unroll
        for (int mt = 0; mt < 2; mt++)
#pragma unroll
            for (int nt = 0; nt < 8; nt++)
#pragma unroll
                for (int c = 0; c < 4; c++) {
                    float v = s[mt][nt][c] * sc;
                    if (need_mask) {
                        int row = q0 + wid * 32 + mt * 16 + (lid >> 2) + ((c >> 1) << 3);
                        int key = k0 + nt * 8 + 2 * (lid & 3) + (c & 1);
                        if (key > row) v = -1e30f;
                    }
                    s[mt][nt][c] = v;
                }

        // ---- online softmax (rows live in 4-lane groups) ----
#pragma unroll
        for (int mt = 0; mt < 2; mt++)
#pragma unroll
            for (int hf = 0; hf < 2; hf++) {
                const int ri = mt * 2 + hf;
                float mx = -1e30f;
#pragma unroll
                for (int nt = 0; nt < 8; nt++) {
                    mx = fmaxf(mx, s[mt][nt][hf * 2]);
                    mx = fmaxf(mx, s[mt][nt][hf * 2 + 1]);
                }
                mx = fmaxf(mx, __shfl_xor_sync(0xffffffff, mx, 1));
                mx = fmaxf(mx, __shfl_xor_sync(0xffffffff, mx, 2));
                float mnew = fmaxf(mrow[ri], mx);
                float corr = fast_exp(mrow[ri] - mnew);
                mrow[ri] = mnew;
                float lsum = 0.0f;
#pragma unroll
                for (int nt = 0; nt < 8; nt++) {
                    float p0 = fast_exp(s[mt][nt][hf * 2] - mnew);
                    float p1 = fast_exp(s[mt][nt][hf * 2 + 1] - mnew);
                    s[mt][nt][hf * 2] = p0;
                    s[mt][nt][hf * 2 + 1] = p1;
                    lsum += p0 + p1;
                }
                lsum += __shfl_xor_sync(0xffffffff, lsum, 1);
                lsum += __shfl_xor_sync(0xffffffff, lsum, 2);
                lrow[ri] = lrow[ri] * corr + lsum;
#pragma unroll
                for (int dt = 0; dt < 8; dt++) {
                    o[mt][dt][hf * 2] *= corr;
                    o[mt][dt][hf * 2 + 1] *= corr;
                }
            }

        // ---- O += P V (3-term) ----
#pragma unroll
        for (int kk = 0; kk < 4; kk++) {
            uint32_t ph[2][4], pl[2][4];
#pragma unroll
            for (int mt = 0; mt < 2; mt++) {
#pragma unroll
                for (int half = 0; half < 2; half++) {   // ntile 2kk+half
                    float p0 = s[mt][2 * kk + half][0], p1 = s[mt][2 * kk + half][1];
                    float p2 = s[mt][2 * kk + half][2], p3 = s[mt][2 * kk + half][3];
                    __nv_bfloat16 h0 = __float2bfloat16(p0), h1 = __float2bfloat16(p1);
                    __nv_bfloat16 h2 = __float2bfloat16(p2), h3 = __float2bfloat16(p3);
                    ph[mt][half * 2 + 0] = pack_bf2(h0, h1);
                    ph[mt][half * 2 + 1] = pack_bf2(h2, h3);
                    pl[mt][half * 2 + 0] = pack_bf2(
                        __float2bfloat16(p0 - __bfloat162float(h0)),
                        __float2bfloat16(p1 - __bfloat162float(h1)));
                    pl[mt][half * 2 + 1] = pack_bf2(
                        __float2bfloat16(p2 - __bfloat162float(h2)),
                        __float2bfloat16(p3 - __bfloat162float(h3)));
                }
            }
            uint32_t vh[4][4], vl[4][4];
#pragma unroll
            for (int dp = 0; dp < 4; dp++) {
                uint32_t off = SWZ((uint32_t)(
                    (kk * 16 + (qq & 1) * 8 + rin) * 128 + dp * 32 + (qq >> 1) * 16));
                ldsm4t(vh[dp], stb + 16384 + off);
                ldsm4t(vl[dp], stb + 24576 + off);
            }
#pragma unroll
            for (int mt = 0; mt < 2; mt++)
#pragma unroll
                for (int dt = 0; dt < 8; dt++) {
                    const uint32_t* bhp = &vh[dt >> 1][(dt & 1) * 2];
                    const uint32_t* blp = &vl[dt >> 1][(dt & 1) * 2];
                    mma_bf16(o[mt][dt], ph[mt], bhp);
                    mma_bf16(o[mt][dt], ph[mt], blp);
                    mma_bf16(o[mt][dt], pl[mt], bhp);
                }
        }
        __syncthreads();
    }

    // ---- epilogue: normalize, split hi/lo, write [row, E] layout ----
    float inv[4];
#pragma unroll
    for (int ri = 0; ri < 4; ri++) inv[ri] = 1.0f / lrow[ri];

#pragma unroll
    for (int mt = 0; mt < 2; mt++)
#pragma unroll
        for (int dt = 0; dt < 8; dt++) {
            int col = h * 64 + dt * 8 + 2 * (lid & 3);
#pragma unroll
            for (int hf = 0; hf < 2; hf++) {
                int row = q0 + wid * 32 + mt * 16 + (lid >> 2) + hf * 8;
                float v0 = o[mt][dt][hf * 2] * inv[mt * 2 + hf];
                float v1 = o[mt][dt][hf * 2 + 1] * inv[mt * 2 + hf];
                size_t idx = ((size_t)(b * SS + row)) * EE + col;
                __nv_bfloat16 h0 = __float2bfloat16(v0), h1 = __float2bfloat16(v1);
                *reinterpret_cast<uint32_t*>(ohi + idx) = pack_bf2(h0, h1);
                *reinterpret_cast<uint32_t*>(olo + idx) = pack_bf2(
                    __float2bfloat16(v0 - __bfloat162float(h0)),
                    __float2bfloat16(v1 - __bfloat162float(h1)));
            }
        }
}

// ---------------------------------------------------------------------------
// Launch
// ---------------------------------------------------------------------------
extern "C" void kernel_launch(void* const* d_in, const int* in_sizes, int n_in,
                              void* d_out, int out_size) {
    const float* x  = (const float*)d_in[0];
    const float* Wq = (const float*)d_in[1];
    const float* Wk = (const float*)d_in[2];
    const float* Wv = (const float*)d_in[3];
    const float* Wo = (const float*)d_in[4];
    float* out = (float*)d_out;

    __nv_bfloat16 *ahi, *alo, *whi, *wlo, *qhi, *qlo, *khi, *klo, *vhi, *vlo;
    cudaGetSymbolAddress((void**)&ahi, g_ahi);
    cudaGetSymbolAddress((void**)&alo, g_alo);
    cudaGetSymbolAddress((void**)&whi, g_whi);
    cudaGetSymbolAddress((void**)&wlo, g_wlo);
    cudaGetSymbolAddress((void**)&qhi, g_qhi);
    cudaGetSymbolAddress((void**)&qlo, g_qlo);
    cudaGetSymbolAddress((void**)&khi, g_khi);
    cudaGetSymbolAddress((void**)&klo, g_klo);
    cudaGetSymbolAddress((void**)&vhi, g_vhi);
    cudaGetSymbolAddress((void**)&vlo, g_vlo);

    cudaFuncSetAttribute(gemm_mma, cudaFuncAttributeMaxDynamicSharedMemorySize,
                         GEMM_SMEM);
    cudaFuncSetAttribute(flash_mma, cudaFuncAttributeMaxDynamicSharedMemorySize,
                         FLASH_SMEM);

    const int nA = MROWS * EE;
    const int nW = EE * EE;
    dim3 gg(EE / BN, MROWS / BM);   // (8, 32)

    rope_table_kernel<<<64, 1024>>>();
    split_kernel<<<(nA + 255) / 256, 256>>>(x, ahi, alo, nA);

    split_kernel<<<(nW + 255) / 256, 256>>>(Wq, whi, wlo, nW);
    gemm_mma<<<gg, 256, GEMM_SMEM>>>(ahi, alo, whi, wlo, nullptr, qhi, qlo, 1);

    split_kernel<<<(nW + 255) / 256, 256>>>(Wk, whi, wlo, nW);
    gemm_mma<<<gg, 256, GEMM_SMEM>>>(ahi, alo, whi, wlo, nullptr, khi, klo, 1);

    split_kernel<<<(nW + 255) / 256, 256>>>(Wv, whi, wlo, nW);
    gemm_mma<<<gg, 256, GEMM_SMEM>>>(ahi, alo, whi, wlo, nullptr, vhi, vlo, 2);

    dim3 fg(SS / FQ, BB * HH);      // (16, 32)
    flash_mma<<<fg, 128, FLASH_SMEM>>>(qhi, qlo, khi, klo, vhi, vlo, ahi, alo);

    split_kernel<<<(nW + 255) / 256, 256>>>(Wo, whi, wlo, nW);
    gemm_mma<<<gg, 256, GEMM_SMEM>>>(ahi, alo, whi, wlo, out, nullptr, nullptr, 0);
}

// round 6
// speedup vs baseline: 5.9782x; 1.0702x over previous
#include <cuda_runtime.h>
#include <cuda_bf16.h>
#include <math.h>
#include <stdint.h>

// Problem constants
#define BB 2
#define SS 2048
#define EE 1024
#define HH 16
#define DD 64
#define MROWS (BB * SS)   // 4096
#define NW (EE * EE)      // 1048576

// Scratch (__device__ globals; allocation-free rule)
__device__ __nv_bfloat16 g_ahi[MROWS * EE];
__device__ __nv_bfloat16 g_alo[MROWS * EE];
__device__ __nv_bfloat16 g_whi[4 * NW];
__device__ __nv_bfloat16 g_wlo[4 * NW];
__device__ __nv_bfloat16 g_qhi[MROWS * EE];
__device__ __nv_bfloat16 g_qlo[MROWS * EE];
__device__ __nv_bfloat16 g_khi[MROWS * EE];
__device__ __nv_bfloat16 g_klo[MROWS * EE];
__device__ __nv_bfloat16 g_vhi[MROWS * EE];
__device__ __nv_bfloat16 g_vlo[MROWS * EE];
__device__ float2 g_rope[SS * 32];

// ---------------------------------------------------------------------------
// Helpers
// ---------------------------------------------------------------------------
static __device__ __forceinline__ uint32_t smem_u32(const void* p) {
    uint32_t a;
    asm("{ .reg .u64 t; cvta.to.shared.u64 t, %1; cvt.u32.u64 %0, t; }"
        : "=r"(a) : "l"(p));
    return a;
}

#define SWZ(o)   ((o) ^ (((o) >> 3) & 0x70))
#define SWZ64(o) ((o) ^ (((o) >> 3) & 0x30))

static __device__ __forceinline__ void cp16(uint32_t saddr, const void* g) {
    asm volatile("cp.async.cg.shared.global [%0], [%1], 16;"
                 :: "r"(saddr), "l"(g));
}
#define CP_COMMIT() asm volatile("cp.async.commit_group;")
#define CP_WAIT(n)  asm volatile("cp.async.wait_group %0;" :: "n"(n))

static __device__ __forceinline__ void ldsm4(uint32_t* r, uint32_t addr) {
    asm volatile("ldmatrix.sync.aligned.m8n8.x4.shared.b16 {%0,%1,%2,%3}, [%4];"
                 : "=r"(r[0]), "=r"(r[1]), "=r"(r[2]), "=r"(r[3]) : "r"(addr));
}

static __device__ __forceinline__ void ldsm4t(uint32_t* r, uint32_t addr) {
    asm volatile("ldmatrix.sync.aligned.m8n8.x4.trans.shared.b16 {%0,%1,%2,%3}, [%4];"
                 : "=r"(r[0]), "=r"(r[1]), "=r"(r[2]), "=r"(r[3]) : "r"(addr));
}

static __device__ __forceinline__ void mma_bf16(float* c, const uint32_t* a,
                                                const uint32_t* b) {
    asm volatile(
        "mma.sync.aligned.m16n8k16.row.col.f32.bf16.bf16.f32 "
        "{%0,%1,%2,%3}, {%4,%5,%6,%7}, {%8,%9}, {%0,%1,%2,%3};"
        : "+f"(c[0]), "+f"(c[1]), "+f"(c[2]), "+f"(c[3])
        : "r"(a[0]), "r"(a[1]), "r"(a[2]), "r"(a[3]), "r"(b[0]), "r"(b[1]));
}

// FFMA-only exp (no MUFU)
static __device__ __forceinline__ float fast_exp(float x) {
    float t = x * 1.4426950408889634f;
    t = fmaxf(t, -126.0f);
    float fn = t + 12582912.0f;
    int n = __float_as_int(fn) - 0x4B400000;
    float f = t - (fn - 12582912.0f);
    float r = 0.0013333558f;
    r = fmaf(r, f, 0.0096181291f);
    r = fmaf(r, f, 0.0555041087f);
    r = fmaf(r, f, 0.2402265069f);
    r = fmaf(r, f, 0.6931471806f);
    r = fmaf(r, f, 1.0f);
    return __int_as_float(__float_as_int(r) + (n << 23));
}

static __device__ __forceinline__ uint32_t pack_bf2(__nv_bfloat16 lo, __nv_bfloat16 hi) {
    __nv_bfloat162 v = {lo, hi};
    return *reinterpret_cast<uint32_t*>(&v);
}

// ---------------------------------------------------------------------------
// rope cos/sin table
// ---------------------------------------------------------------------------
__global__ void rope_table_kernel() {
    int idx = blockIdx.x * blockDim.x + threadIdx.x;
    if (idx >= SS * 32) return;
    int s = idx >> 5, i = idx & 31;
    float theta = expf(-logf(10000.0f) * (2.0f * (float)i) / 64.0f);
    float c, sn;
    sincosf((float)s * theta, &sn, &c);
    g_rope[idx] = make_float2(c, sn);
}

// ---------------------------------------------------------------------------
// fp32 -> bf16 hi/lo split, float4 vectorized. n4 = n/4 elements of float4.
// ---------------------------------------------------------------------------
static __device__ __forceinline__ void split4_store(
    float4 v, __nv_bfloat16* hi, __nv_bfloat16* lo, size_t i4) {
    __nv_bfloat16 h0 = __float2bfloat16(v.x), h1 = __float2bfloat16(v.y);
    __nv_bfloat16 h2 = __float2bfloat16(v.z), h3 = __float2bfloat16(v.w);
    uint2 ph = make_uint2(pack_bf2(h0, h1), pack_bf2(h2, h3));
    uint2 pl = make_uint2(
        pack_bf2(__float2bfloat16(v.x - __bfloat162float(h0)),
                 __float2bfloat16(v.y - __bfloat162float(h1))),
        pack_bf2(__float2bfloat16(v.z - __bfloat162float(h2)),
                 __float2bfloat16(v.w - __bfloat162float(h3))));
    reinterpret_cast<uint2*>(hi)[i4] = ph;
    reinterpret_cast<uint2*>(lo)[i4] = pl;
}

__global__ void split_x_kernel(const float* __restrict__ src,
                               __nv_bfloat16* __restrict__ hi,
                               __nv_bfloat16* __restrict__ lo, int n4) {
    int i = blockIdx.x * blockDim.x + threadIdx.x;
    if (i >= n4) return;
    split4_store(reinterpret_cast<const float4*>(src)[i], hi, lo, i);
}

// Splits Wq,Wk,Wv,Wo into g_whi/g_wlo slices. 4*NW/4 threads.
__global__ void split_w_kernel(const float* __restrict__ w0,
                               const float* __restrict__ w1,
                               const float* __restrict__ w2,
                               const float* __restrict__ w3,
                               __nv_bfloat16* __restrict__ hi,
                               __nv_bfloat16* __restrict__ lo) {
    int i = blockIdx.x * blockDim.x + threadIdx.x;   // 0 .. 4*NW/4-1
    int z = i >> 18;                                  // NW/4 = 262144 = 2^18
    int loc = i & 0x3FFFF;
    const float* w = (z == 0) ? w0 : (z == 1) ? w1 : (z == 2) ? w2 : w3;
    split4_store(reinterpret_cast<const float4*>(w)[loc], hi, lo, i);
}

// ---------------------------------------------------------------------------
// Warp-MMA GEMM: C[M,N] = (Ahi+Alo)[M,K] @ (W[z]hi+W[z]lo)[N,K]^T.
// CTA 128x64, 4 warps (warp tile 64x32), BK=32, 3-stage cp.async, SW64.
// fused=1: grid.z in {0,1,2} -> (Q rope), (K rope), (V) split-bf16 BHSD out.
// fused=0: fp32 C out (Wo slice passed via pointer offset by caller).
// ---------------------------------------------------------------------------
#define BM 128
#define BN 64
#define BK 32
#define KTILES (EE / BK)                 // 32
#define A_T (BM * BK * 2)                // 8192
#define B_T (BN * BK * 2)                // 4096
#define STAGE_B (2 * A_T + 2 * B_T)      // 24576
#define GEMM_SMEM (3 * STAGE_B)          // 73728

__global__ void __launch_bounds__(128, 3) gemm_mma(
    const __nv_bfloat16* __restrict__ Ahi, const __nv_bfloat16* __restrict__ Alo,
    const __nv_bfloat16* __restrict__ Whi, const __nv_bfloat16* __restrict__ Wlo,
    float* __restrict__ C,
    __nv_bfloat16* __restrict__ qhi, __nv_bfloat16* __restrict__ qlo,
    __nv_bfloat16* __restrict__ khi, __nv_bfloat16* __restrict__ klo,
    __nv_bfloat16* __restrict__ vhi, __nv_bfloat16* __restrict__ vlo,
    int fused) {
    extern __shared__ __align__(1024) char smem[];
    const uint32_t sb = smem_u32(smem);

    const int tid = threadIdx.x;
    const int wid = tid >> 5;
    const int lid = tid & 31;
    const int row0 = blockIdx.y * BM;
    const int col0 = blockIdx.x * BN;
    const int wm = wid & 1;
    const int wn = wid >> 1;              // 0..1
    const int z = blockIdx.z;

    const __nv_bfloat16* Bhi = Whi + (size_t)z * NW;
    const __nv_bfloat16* Blo = Wlo + (size_t)z * NW;

    const int O_AHI = 0, O_ALO = A_T, O_BHI = 2 * A_T, O_BLO = 2 * A_T + B_T;

    float acc[4][4][4] = {};

    auto load_tiles = [&](int st, int kt) {
        const uint32_t stb = sb + st * STAGE_B;
        const int k0 = kt * BK;
#pragma unroll
        for (int i = 0; i < 4; i++) {
            int c = tid + i * 128;        // 0..511
            int r = c >> 2;               // 0..127
            int cb = (c & 3) * 16;
            uint32_t so = SWZ64((uint32_t)(r * 64 + cb));
            size_t ga = (size_t)(row0 + r) * EE + k0 + (c & 3) * 8;
            cp16(stb + O_AHI + so, Ahi + ga);
            cp16(stb + O_ALO + so, Alo + ga);
        }
#pragma unroll
        for (int i = 0; i < 2; i++) {
            int c = tid + i * 128;        // 0..255
            int r = c >> 2;               // 0..63
            int cb = (c & 3) * 16;
            uint32_t so = SWZ64((uint32_t)(r * 64 + cb));
            size_t gb = (size_t)(col0 + r) * EE + k0 + (c & 3) * 8;
            cp16(stb + O_BHI + so, Bhi + gb);
            cp16(stb + O_BLO + so, Blo + gb);
        }
    };

    load_tiles(0, 0);
    CP_COMMIT();
    load_tiles(1, 1);
    CP_COMMIT();

    const int q = lid >> 3, rin = lid & 7;

    for (int kt = 0; kt < KTILES; kt++) {
        if (kt < KTILES - 1) { CP_WAIT(1); } else { CP_WAIT(0); }
        __syncthreads();
        if (kt + 2 < KTILES) {
            int st = kt + 2;
            st = st - (st / 3) * 3;
            load_tiles(st, kt + 2);
            CP_COMMIT();
        }

        const int cur = kt - (kt / 3) * 3;
        const uint32_t stb = sb + cur * STAGE_B;

#pragma unroll
        for (int ks = 0; ks < 2; ks++) {
            const int kb = ks * 32;
            uint32_t ahi[4][4], alo[4][4], bhi[2][4], blo[2][4];
#pragma unroll
            for (int mt = 0; mt < 4; mt++) {
                uint32_t off = SWZ64((uint32_t)(
                    (wm * 64 + mt * 16 + (q & 1) * 8 + rin) * 64 + kb + (q >> 1) * 16));
                ldsm4(ahi[mt], stb + O_AHI + off);
                ldsm4(alo[mt], stb + O_ALO + off);
            }
#pragma unroll
            for (int p = 0; p < 2; p++) {
                uint32_t off = SWZ64((uint32_t)(
                    (wn * 32 + p * 16 + (q >> 1) * 8 + rin) * 64 + kb + (q & 1) * 16));
                ldsm4(bhi[p], stb + O_BHI + off);
                ldsm4(blo[p], stb + O_BLO + off);
            }
#pragma unroll
            for (int mt = 0; mt < 4; mt++)
#pragma unroll
                for (int nt = 0; nt < 4; nt++) {
                    const uint32_t* bh = &bhi[nt >> 1][(nt & 1) * 2];
                    const uint32_t* bl = &blo[nt >> 1][(nt & 1) * 2];
                    mma_bf16(acc[mt][nt], ahi[mt], bh);
                    mma_bf16(acc[mt][nt], ahi[mt], bl);
                    mma_bf16(acc[mt][nt], alo[mt], bh);
                }
        }
    }

    const int r_base = row0 + wm * 64 + (lid >> 2);
    const int c_base = col0 + wn * 32 + (lid & 3) * 2;

    if (!fused) {
#pragma unroll
        for (int mt = 0; mt < 4; mt++)
#pragma unroll
            for (int nt = 0; nt < 4; nt++) {
                int r = r_base + mt * 16;
                int c = c_base + nt * 8;
                *reinterpret_cast<float2*>(C + (size_t)r * EE + c) =
                    make_float2(acc[mt][nt][0], acc[mt][nt][1]);
                *reinterpret_cast<float2*>(C + (size_t)(r + 8) * EE + c) =
                    make_float2(acc[mt][nt][2], acc[mt][nt][3]);
            }
    } else {
        __nv_bfloat16* Dhi = (z == 0) ? qhi : (z == 1) ? khi : vhi;
        __nv_bfloat16* Dlo = (z == 0) ? qlo : (z == 1) ? klo : vlo;
        const int mode = (z == 2) ? 2 : 1;
#pragma unroll
        for (int mt = 0; mt < 4; mt++)
#pragma unroll
            for (int nt = 0; nt < 4; nt++) {
                int gr = r_base + mt * 16;
                int gc = c_base + nt * 8;
                int hh = gc >> 6, d = gc & 63, ii = d >> 1;
                int b_ = gr >> 11;
                int s1 = gr & (SS - 1);
                int s2 = (gr + 8) & (SS - 1);
                float v0 = acc[mt][nt][0], v1 = acc[mt][nt][1];
                float v2 = acc[mt][nt][2], v3 = acc[mt][nt][3];
                if (mode == 1) {
                    float2 cs1 = g_rope[(s1 << 5) + ii];
                    float2 cs2 = g_rope[(s2 << 5) + ii];
                    float t0 = v0 * cs1.x - v1 * cs1.y;
                    v1 = v0 * cs1.y + v1 * cs1.x; v0 = t0;
                    t0 = v2 * cs2.x - v3 * cs2.y;
                    v3 = v2 * cs2.y + v3 * cs2.x; v2 = t0;
                }
                size_t o1 = ((size_t)((b_ * HH + hh) * SS + s1)) * 64 + d;
                size_t o2 = ((size_t)((b_ * HH + hh) * SS + s2)) * 64 + d;
                __nv_bfloat16 h0 = __float2bfloat16(v0), h1 = __float2bfloat16(v1);
                __nv_bfloat16 h2 = __float2bfloat16(v2), h3 = __float2bfloat16(v3);
                *reinterpret_cast<uint32_t*>(Dhi + o1) = pack_bf2(h0, h1);
                *reinterpret_cast<uint32_t*>(Dhi + o2) = pack_bf2(h2, h3);
                *reinterpret_cast<uint32_t*>(Dlo + o1) = pack_bf2(
                    __float2bfloat16(v0 - __bfloat162float(h0)),
                    __float2bfloat16(v1 - __bfloat162float(h1)));
                *reinterpret_cast<uint32_t*>(Dlo + o2) = pack_bf2(
                    __float2bfloat16(v2 - __bfloat162float(h2)),
                    __float2bfloat16(v3 - __bfloat162float(h3)));
            }
    }
}

// ---------------------------------------------------------------------------
// Warp-MMA causal flash attention (unchanged from round 5).
// ---------------------------------------------------------------------------
#define FQ 128
#define FK 64
#define Q_B 16384
#define KV_STAGE 32768
#define FLASH_SMEM (2 * Q_B + 2 * KV_STAGE)   // 98304

__global__ void __launch_bounds__(128) flash_mma(
    const __nv_bfloat16* __restrict__ qhi, const __nv_bfloat16* __restrict__ qlo,
    const __nv_bfloat16* __restrict__ khi, const __nv_bfloat16* __restrict__ klo,
    const __nv_bfloat16* __restrict__ vhi, const __nv_bfloat16* __restrict__ vlo,
    __nv_bfloat16* __restrict__ ohi, __nv_bfloat16* __restrict__ olo) {
    extern __shared__ __align__(1024) char smem[];
    const uint32_t sb = smem_u32(smem);
    const int tid = threadIdx.x;
    const int wid = tid >> 5;
    const int lid = tid & 31;
    const int bh = blockIdx.y;
    const int qt = gridDim.x - 1 - blockIdx.x;
    const int q0 = qt * FQ;
    const int b = bh >> 4, h = bh & 15;

#pragma unroll
    for (int i = 0; i < 8; i++) {
        int c = i * 128 + tid;
        int r = c >> 3, cb = c & 7;
        uint32_t so = SWZ((uint32_t)(r * 128 + cb * 16));
        size_t g = ((size_t)bh * SS + q0 + r) * 64 + cb * 8;
        cp16(sb + so, qhi + g);
        cp16(sb + Q_B + so, qlo + g);
    }
    CP_COMMIT();

    auto load_kv = [&](int st, int kt) {
        const uint32_t stb = sb + 2 * Q_B + st * KV_STAGE;
        const size_t rb = (size_t)bh * SS + (size_t)kt * FK;
#pragma unroll
        for (int i = 0; i < 4; i++) {
            int c = i * 128 + tid;
            int r = c >> 3, cb = c & 7;
            uint32_t so = SWZ((uint32_t)(r * 128 + cb * 16));
            size_t g = (rb + r) * 64 + cb * 8;
            cp16(stb + so,         khi + g);
            cp16(stb + 8192 + so,  klo + g);
            cp16(stb + 16384 + so, vhi + g);
            cp16(stb + 24576 + so, vlo + g);
        }
    };

    float o[2][8][4] = {};
    float mrow[4] = {-1e30f, -1e30f, -1e30f, -1e30f};
    float lrow[4] = {};

    const int nkt = 2 * qt + 2;
    load_kv(0, 0);
    CP_COMMIT();

    const int qq = lid >> 3, rin = lid & 7;
    const float sc = 1.0f / 32.0f;

    for (int kt = 0; kt < nkt; kt++) {
        if (kt + 1 < nkt) {
            load_kv((kt + 1) & 1, kt + 1);
            CP_COMMIT();
            CP_WAIT(1);
        } else {
            CP_WAIT(0);
        }
        __syncthreads();

        const uint32_t stb = sb + 2 * Q_B + (kt & 1) * KV_STAGE;
        const int k0 = kt * FK;

        float s[2][8][4] = {};
#pragma unroll
        for (int kd = 0; kd < 4; kd++) {
            uint32_t qh[2][4], ql[2][4];
#pragma unroll
            for (int mt = 0; mt < 2; mt++) {
                uint32_t off = SWZ((uint32_t)(
                    (wid * 32 + mt * 16 + (qq & 1) * 8 + rin) * 128 +
                    kd * 32 + (qq >> 1) * 16));
                ldsm4(qh[mt], sb + off);
                ldsm4(ql[mt], sb + Q_B + off);
            }
            uint32_t kh[4][4], kl[4][4];
#pragma unroll
            for (int p = 0; p < 4; p++) {
                uint32_t off = SWZ((uint32_t)(
                    (p * 16 + (qq >> 1) * 8 + rin) * 128 + kd * 32 + (qq & 1) * 16));
                ldsm4(kh[p], stb + off);
                ldsm4(kl[p], stb + 8192 + off);
            }
#pragma unroll
            for (int mt = 0; mt < 2; mt++)
#pragma unroll
                for (int nt = 0; nt < 8; nt++) {
                    const uint32_t* bhp = &kh[nt >> 1][(nt & 1) * 2];
                    const uint32_t* blp = &kl[nt >> 1][(nt & 1) * 2];
                    mma_bf16(s[mt][nt], qh[mt], bhp);
                    mma_bf16(s[mt][nt], qh[mt], blp);
                    mma_bf16(s[mt][nt], ql[mt], bhp);
                }
        }

        const bool need_mask = (k0 + FK - 1) > (q0 + wid * 32);
#pragma unroll
        for (int mt = 0; mt < 2; mt++)
#pragma unroll
            for (int nt = 0; nt < 8; nt++)
#pragma unroll
                for (int c = 0; c < 4; c++) {
                    float v = s[mt][nt][c] * sc;
                    if (need_mask) {
                        int row = q0 + wid * 32 + mt * 16 + (lid >> 2) + ((c >> 1) << 3);
                        int key = k0 + nt * 8 + 2 * (lid & 3) + (c & 1);
                        if (key > row) v = -1e30f;
                    }
                    s[mt][nt][c] = v;
                }

#pragma unroll
        for (int mt = 0; mt < 2; mt++)
#pragma unroll
            for (int hf = 0; hf < 2; hf++) {
                const int ri = mt * 2 + hf;
                float mx = -1e30f;
#pragma unroll
                for (int nt = 0; nt < 8; nt++) {
                    mx = fmaxf(mx, s[mt][nt][hf * 2]);
                    mx = fmaxf(mx, s[mt][nt][hf * 2 + 1]);
                }
                mx = fmaxf(mx, __shfl_xor_sync(0xffffffff, mx, 1));
                mx = fmaxf(mx, __shfl_xor_sync(0xffffffff, mx, 2));
                float mnew = fmaxf(mrow[ri], mx);
                float corr = fast_exp(mrow[ri] - mnew);
                mrow[ri] = mnew;
                float lsum = 0.0f;
#pragma unroll
                for (int nt = 0; nt < 8; nt++) {
                    float p0 = fast_exp(s[mt][nt][hf * 2] - mnew);
                    float p1 = fast_exp(s[mt][nt][hf * 2 + 1] - mnew);
                    s[mt][nt][hf * 2] = p0;
                    s[mt][nt][hf * 2 + 1] = p1;
                    lsum += p0 + p1;
                }
                lsum += __shfl_xor_sync(0xffffffff, lsum, 1);
                lsum += __shfl_xor_sync(0xffffffff, lsum, 2);
                lrow[ri] = lrow[ri] * corr + lsum;
#pragma unroll
                for (int dt = 0; dt < 8; dt++) {
                    o[mt][dt][hf * 2] *= corr;
                    o[mt][dt][hf * 2 + 1] *= corr;
                }
            }

#pragma unroll
        for (int kk = 0; kk < 4; kk++) {
            uint32_t ph[2][4], pl[2][4];
#pragma unroll
            for (int mt = 0; mt < 2; mt++) {
#pragma unroll
                for (int half = 0; half < 2; half++) {
                    float p0 = s[mt][2 * kk + half][0], p1 = s[mt][2 * kk + half][1];
                    float p2 = s[mt][2 * kk + half][2], p3 = s[mt][2 * kk + half][3];
                    __nv_bfloat16 h0 = __float2bfloat16(p0), h1 = __float2bfloat16(p1);
                    __nv_bfloat16 h2 = __float2bfloat16(p2), h3 = __float2bfloat16(p3);
                    ph[mt][half * 2 + 0] = pack_bf2(h0, h1);
                    ph[mt][half * 2 + 1] = pack_bf2(h2, h3);
                    pl[mt][half * 2 + 0] = pack_bf2(
                        __float2bfloat16(p0 - __bfloat162float(h0)),
                        __float2bfloat16(p1 - __bfloat162float(h1)));
                    pl[mt][half * 2 + 1] = pack_bf2(
                        __float2bfloat16(p2 - __bfloat162float(h2)),
                        __float2bfloat16(p3 - __bfloat162float(h3)));
                }
            }
            uint32_t vh[4][4], vl[4][4];
#pragma unroll
            for (int dp = 0; dp < 4; dp++) {
                uint32_t off = SWZ((uint32_t)(
                    (kk * 16 + (qq & 1) * 8 + rin) * 128 + dp * 32 + (qq >> 1) * 16));
                ldsm4t(vh[dp], stb + 16384 + off);
                ldsm4t(vl[dp], stb + 24576 + off);
            }
#pragma unroll
            for (int mt = 0; mt < 2; mt++)
#pragma unroll
                for (int dt = 0; dt < 8; dt++) {
                    const uint32_t* bhp = &vh[dt >> 1][(dt & 1) * 2];
                    const uint32_t* blp = &vl[dt >> 1][(dt & 1) * 2];
                    mma_bf16(o[mt][dt], ph[mt], bhp);
                    mma_bf16(o[mt][dt], ph[mt], blp);
                    mma_bf16(o[mt][dt], pl[mt], bhp);
                }
        }
        __syncthreads();
    }

    float inv[4];
#pragma unroll
    for (int ri = 0; ri < 4; ri++) inv[ri] = 1.0f / lrow[ri];

#pragma unroll
    for (int mt = 0; mt < 2; mt++)
#pragma unroll
        for (int dt = 0; dt < 8; dt++) {
            int col = h * 64 + dt * 8 + 2 * (lid & 3);
#pragma unroll
            for (int hf = 0; hf < 2; hf++) {
                int row = q0 + wid * 32 + mt * 16 + (lid >> 2) + hf * 8;
                float v0 = o[mt][dt][hf * 2] * inv[mt * 2 + hf];
                float v1 = o[mt][dt][hf * 2 + 1] * inv[mt * 2 + hf];
                size_t idx = ((size_t)(b * SS + row)) * EE + col;
                __nv_bfloat16 h0 = __float2bfloat16(v0), h1 = __float2bfloat16(v1);
                *reinterpret_cast<uint32_t*>(ohi + idx) = pack_bf2(h0, h1);
                *reinterpret_cast<uint32_t*>(olo + idx) = pack_bf2(
                    __float2bfloat16(v0 - __bfloat162float(h0)),
                    __float2bfloat16(v1 - __bfloat162float(h1)));
            }
        }
}

// ---------------------------------------------------------------------------
// Launch
// ---------------------------------------------------------------------------
extern "C" void kernel_launch(void* const* d_in, const int* in_sizes, int n_in,
                              void* d_out, int out_size) {
    const float* x  = (const float*)d_in[0];
    const float* Wq = (const float*)d_in[1];
    const float* Wk = (const float*)d_in[2];
    const float* Wv = (const float*)d_in[3];
    const float* Wo = (const float*)d_in[4];
    float* out = (float*)d_out;

    __nv_bfloat16 *ahi, *alo, *whi, *wlo, *qhi, *qlo, *khi, *klo, *vhi, *vlo;
    cudaGetSymbolAddress((void**)&ahi, g_ahi);
    cudaGetSymbolAddress((void**)&alo, g_alo);
    cudaGetSymbolAddress((void**)&whi, g_whi);
    cudaGetSymbolAddress((void**)&wlo, g_wlo);
    cudaGetSymbolAddress((void**)&qhi, g_qhi);
    cudaGetSymbolAddress((void**)&qlo, g_qlo);
    cudaGetSymbolAddress((void**)&khi, g_khi);
    cudaGetSymbolAddress((void**)&klo, g_klo);
    cudaGetSymbolAddress((void**)&vhi, g_vhi);
    cudaGetSymbolAddress((void**)&vlo, g_vlo);

    cudaFuncSetAttribute(gemm_mma, cudaFuncAttributeMaxDynamicSharedMemorySize,
                         GEMM_SMEM);
    cudaFuncSetAttribute(flash_mma, cudaFuncAttributeMaxDynamicSharedMemorySize,
                         FLASH_SMEM);

    rope_table_kernel<<<64, 1024>>>();
    split_x_kernel<<<(MROWS * EE / 4 + 255) / 256, 256>>>(x, ahi, alo, MROWS * EE / 4);
    split_w_kernel<<<(4 * NW / 4 + 255) / 256, 256>>>(Wq, Wk, Wv, Wo, whi, wlo);

    // Fused QKV GEMMs (z selects weight slice + epilogue)
    dim3 gq(EE / BN, MROWS / BM, 3);   // (16, 32, 3)
    gemm_mma<<<gq, 128, GEMM_SMEM>>>(ahi, alo, whi, wlo, nullptr,
                                     qhi, qlo, khi, klo, vhi, vlo, 1);

    dim3 fg(SS / FQ, BB * HH);         // (16, 32)
    flash_mma<<<fg, 128, FLASH_SMEM>>>(qhi, qlo, khi, klo, vhi, vlo, ahi, alo);

    // Output projection with Wo slice (z=3 offset passed via pointer)
    dim3 go(EE / BN, MROWS / BM, 1);
    gemm_mma<<<go, 128, GEMM_SMEM>>>(ahi, alo, whi + 3 * (size_t)NW,
                                     wlo + 3 * (size_t)NW, out,
                                     nullptr, nullptr, nullptr, nullptr,
                                     nullptr, nullptr, 0);
}